// round 15
// baseline (speedup 1.0000x reference)
#include <cuda_runtime.h>
#include <cstdint>

#define TS 4096
#define NH 16
#define HD 128
#define NP 512
#define BM 64             // queries per CTA
#define BN 32             // keys per chunk
#define NT 128            // 4 warps x 16 queries
#define NCHUNK 48         // 16 base + 2*16 regional
#define SCALE 0.08838834764831845f

// ---- device scratch (layouts unchanged from R12) ----
__device__ uint32_t g_khi[3*16*512*64];
__device__ uint32_t g_klo[3*16*512*64];
__device__ uint32_t g_vtf[3*16*128*256];   // fp16 V^T packed key-pairs
__device__ uint32_t g_qhi[4096*16*64];
__device__ uint32_t g_qlo[4096*16*64];

static __device__ __forceinline__ uint32_t s2u(const void* p){
  uint32_t a; asm("{ .reg .u64 t; cvta.to.shared.u64 t, %1; cvt.u32.u64 %0, t; }" : "=r"(a) : "l"(p)); return a;
}
static __device__ __forceinline__ uint16_t f2bf(float x){
  uint16_t r; asm("cvt.rn.bf16.f32 %0, %1;" : "=h"(r) : "f"(x)); return r;
}
static __device__ __forceinline__ float bf2f(uint16_t b){
  return __uint_as_float(((uint32_t)b) << 16);
}
static __device__ __forceinline__ uint16_t f2h(float x){
  uint16_t r; asm("cvt.rn.f16.f32 %0, %1;" : "=h"(r) : "f"(x)); return r;
}
static __device__ __forceinline__ uint32_t packbf(float x0, float x1){
  uint32_t r; asm("cvt.rn.bf16x2.f32 %0, %1, %2;" : "=r"(r) : "f"(x1), "f"(x0)); return r;
}
static __device__ __forceinline__ uint32_t packh(float x0, float x1){
  uint32_t r; asm("cvt.rn.f16x2.f32 %0, %1, %2;" : "=r"(r) : "f"(x1), "f"(x0)); return r;
}
static __device__ __forceinline__ void splitpair(float x0, float x1, uint32_t& hi, uint32_t& lo){
  hi = packbf(x0, x1);
  float h0 = bf2f((uint16_t)(hi & 0xffffu));
  float h1 = bf2f((uint16_t)(hi >> 16));
  lo = packbf(x0 - h0, x1 - h1);
}
static __device__ __forceinline__ void mma_bf16(float* d, const uint32_t* a, const uint32_t* b){
  asm volatile(
    "mma.sync.aligned.m16n8k16.row.col.f32.bf16.bf16.f32 "
    "{%0,%1,%2,%3}, {%4,%5,%6,%7}, {%8,%9}, {%0,%1,%2,%3};"
    : "+f"(d[0]), "+f"(d[1]), "+f"(d[2]), "+f"(d[3])
    : "r"(a[0]), "r"(a[1]), "r"(a[2]), "r"(a[3]), "r"(b[0]), "r"(b[1]));
}
static __device__ __forceinline__ void mma_f16(float* d, const uint32_t* a, const uint32_t* b){
  asm volatile(
    "mma.sync.aligned.m16n8k16.row.col.f32.f16.f16.f32 "
    "{%0,%1,%2,%3}, {%4,%5,%6,%7}, {%8,%9}, {%0,%1,%2,%3};"
    : "+f"(d[0]), "+f"(d[1]), "+f"(d[2]), "+f"(d[3])
    : "r"(a[0]), "r"(a[1]), "r"(a[2]), "r"(a[3]), "r"(b[0]), "r"(b[1]));
}
static __device__ __forceinline__ void ldsm4(uint32_t& r0, uint32_t& r1, uint32_t& r2, uint32_t& r3, uint32_t addr){
  asm volatile("ldmatrix.sync.aligned.m8n8.x4.shared.b16 {%0,%1,%2,%3}, [%4];"
               : "=r"(r0), "=r"(r1), "=r"(r2), "=r"(r3) : "r"(addr));
}
static __device__ __forceinline__ void cpa16(uint32_t dst, const void* src){
  asm volatile("cp.async.cg.shared.global [%0], [%1], 16;" :: "r"(dst), "l"(src) : "memory");
}
#define CP_COMMIT() asm volatile("cp.async.commit_group;" ::: "memory")
#define CP_WAIT0()  asm volatile("cp.async.wait_group 0;" ::: "memory")

// ================= pre-pass kernels (verified, unchanged) =================
__global__ void prep_k(const float* __restrict__ k, const float* __restrict__ rk){
  int g = blockIdx.x * blockDim.x + threadIdx.x;
  int dp = g & 63; int r = g >> 6;
  int j = r & 511; r >>= 9;
  int h = r & 15;  int blk = r >> 4;
  const float* src = (blk == 0)
    ? (k  + ((size_t)j*NH + h)*HD + dp*2)
    : (rk + (((size_t)(blk-1)*NP + j)*NH + h)*HD + dp*2);
  float2 x = *(const float2*)src;
  uint32_t hi, lo; splitpair(x.x, x.y, hi, lo);
  g_khi[g] = hi; g_klo[g] = lo;
}
__global__ void prep_q(const float* __restrict__ q){
  int g = blockIdx.x * blockDim.x + threadIdx.x;
  float2 x = *(const float2*)(q + (size_t)g*2);
  uint32_t hi, lo; splitpair(x.x, x.y, hi, lo);
  g_qhi[g] = hi; g_qlo[g] = lo;
}
__global__ void prep_v(const float* __restrict__ v, const float* __restrict__ rv){
  __shared__ uint16_t sh[128][66];
  int jt  = blockIdx.x;
  int h   = blockIdx.y;
  int blk = blockIdx.z;
  int tid = threadIdx.x;
  const float* src = (blk == 0) ? v : (rv + (size_t)(blk-1)*NP*NH*HD);
  #pragma unroll
  for (int i = 0; i < 8; i++){
    int f = i*256 + tid;
    int j = f >> 5; int d0 = (f & 31) << 2;
    float4 x = *(const float4*)(src + ((size_t)(jt*64 + j)*NH + h)*HD + d0);
    sh[d0+0][j] = f2h(x.x);
    sh[d0+1][j] = f2h(x.y);
    sh[d0+2][j] = f2h(x.z);
    sh[d0+3][j] = f2h(x.w);
  }
  __syncthreads();
  size_t base = ((size_t)(blk*NH + h)*128)*256 + jt*32;
  #pragma unroll
  for (int i = 0; i < 16; i++){
    int u = i*256 + tid;
    int d = u >> 5; int jp = u & 31;
    g_vtf[base + (size_t)d*256 + jp] = ((uint32_t)sh[d][jp*2+1] << 16) | sh[d][jp*2];
  }
}

// ================= main kernel =================
// smem (u32): QH 64x68, QL 64x68, KH 2x32x68, KL 2x32x68, VF 2x128x20
#define QH_OFF  0
#define QL_OFF  (QH_OFF + 64*68)           // 4352
#define KH_OFF  (QL_OFF + 64*68)           // 8704, + kbuf*32*68
#define KL_OFF  (KH_OFF + 2*32*68)         // 13056
#define VF_OFF  (KL_OFF + 2*32*68)         // 17408, + vslot*128*20
#define SMEM_U32 (VF_OFF + 2*128*20)       // 22528 u32 = 90112 B -> 2 CTAs/SM

static __device__ __forceinline__ void load_chunk(uint32_t sb, int t, int h, int buf, int tid){
  int blk = (t < 16) ? 0 : (1 + ((t - 16) >> 4));
  int j0  = ((t < 16) ? t : ((t - 16) & 15)) * BN;
  const uint32_t* kh = g_khi + ((size_t)(blk*NH + h)*512 + j0)*64;
  const uint32_t* kl = g_klo + ((size_t)(blk*NH + h)*512 + j0)*64;
  const uint32_t* vf = g_vtf + ((size_t)(blk*NH + h)*128)*256 + (j0 >> 1);
  uint32_t kdh = sb + (KH_OFF + buf*32*68)*4u;
  uint32_t kdl = sb + (KL_OFF + buf*32*68)*4u;
  uint32_t vdf = sb + (VF_OFF + buf*128*20)*4u;
  #pragma unroll
  for (int i = 0; i < 4; i++){
    int f = i*NT + tid;                    // 512: K rows 32 x 16 segs
    int row = f >> 4, seg = f & 15;
    cpa16(kdh + (uint32_t)(row*68 + seg*4)*4u, kh + (size_t)row*64 + seg*4);
    cpa16(kdl + (uint32_t)(row*68 + seg*4)*4u, kl + (size_t)row*64 + seg*4);
    int vrow = f >> 2, vseg = f & 3;       // 512: V rows 128 x 4 segs
    cpa16(vdf + (uint32_t)(vrow*20 + vseg*4)*4u, vf + (size_t)vrow*256 + vseg*4);
  }
}

// One 32-key chunk: QK bf16 3-term -> exp -> PV fp16 single-term.
static __device__ __forceinline__ void do_chunk(
    uint32_t sb, int t, int h, int tid,
    uint32_t qa_h, uint32_t qa_l, uint32_t kb_off, uint32_t vb_off,
    float (&o)[16][4], int a0, int a1, float& su0t, float& su1t)
{
  CP_WAIT0();
  __syncthreads();
  if (t + 1 < NCHUNK){
    load_chunk(sb, t+1, h, (t+1)&1, tid);
    CP_COMMIT();
  }

  const uint32_t kh_base = sb + (uint32_t)(KH_OFF + (t&1)*32*68)*4u + kb_off;
  const uint32_t kl_base = kh_base + (uint32_t)(2*32*68)*4u;         // KL_OFF - KH_OFF
  const uint32_t vf_base = sb + (uint32_t)(VF_OFF + (t&1)*128*20)*4u + vb_off;

  // ---- QK^T (3-term bf16): 4 n-tiles over 32 keys, 8 k-steps
  float sf[4][4];
  #pragma unroll
  for (int n = 0; n < 4; n++)
    #pragma unroll
    for (int e = 0; e < 4; e++) sf[n][e] = 0.f;

  #pragma unroll
  for (int ks = 0; ks < 8; ks++){
    uint32_t ah[4], al[4];
    ldsm4(ah[0], ah[1], ah[2], ah[3], qa_h + ks*32u);
    ldsm4(al[0], al[1], al[2], al[3], qa_l + ks*32u);
    uint32_t B[2][4], C[2][4];
    #pragma unroll
    for (int np = 0; np < 2; np++){
      ldsm4(B[np][0], B[np][1], B[np][2], B[np][3], kh_base + (uint32_t)(np*16*68)*4u + ks*32u);
      ldsm4(C[np][0], C[np][1], C[np][2], C[np][3], kl_base + (uint32_t)(np*16*68)*4u + ks*32u);
    }
    #pragma unroll
    for (int np = 0; np < 2; np++){
      mma_bf16(sf[2*np],   ah, &B[np][0]);
      mma_bf16(sf[2*np+1], ah, &B[np][2]);
    }
    #pragma unroll
    for (int np = 0; np < 2; np++){
      mma_bf16(sf[2*np],   ah, &C[np][0]);
      mma_bf16(sf[2*np+1], ah, &C[np][2]);
    }
    #pragma unroll
    for (int np = 0; np < 2; np++){
      mma_bf16(sf[2*np],   al, &B[np][0]);
      mma_bf16(sf[2*np+1], al, &B[np][2]);
    }
  }

  // ---- exp, pack P fp16
  uint32_t pa[4], pb[4];
  float su0 = 0.f, su1 = 0.f;
  #pragma unroll
  for (int n = 0; n < 4; n++){
    float p0 = a0 ? __expf(sf[n][0]*SCALE) : 0.f;
    float p1 = a0 ? __expf(sf[n][1]*SCALE) : 0.f;
    float p2 = a1 ? __expf(sf[n][2]*SCALE) : 0.f;
    float p3 = a1 ? __expf(sf[n][3]*SCALE) : 0.f;
    su0 += p0 + p1; su1 += p2 + p3;
    pa[n] = packh(p0, p1);
    pb[n] = packh(p2, p3);
  }
  su0t += su0; su1t += su1;

  // ---- P@V (fp16): 2 k-steps x 16 n-tiles = 32 MMAs
  #pragma unroll
  for (int s = 0; s < 2; s++){
    uint32_t ph[4] = { pa[2*s], pb[2*s], pa[2*s+1], pb[2*s+1] };
    #pragma unroll
    for (int g = 0; g < 2; g++){
      uint32_t B[4][4];
      #pragma unroll
      for (int i = 0; i < 4; i++){
        int np = g*4 + i;
        ldsm4(B[i][0], B[i][1], B[i][2], B[i][3], vf_base + (uint32_t)(np*16*20)*4u + s*32u);
      }
      #pragma unroll
      for (int i = 0; i < 4; i++){
        int np = g*4 + i;
        mma_f16(o[2*np],   ph, &B[i][0]);
        mma_f16(o[2*np+1], ph, &B[i][2]);
      }
    }
  }
}

__global__ __launch_bounds__(NT, 2)
void regional_attn_main(const int* __restrict__ masks, float* __restrict__ out)
{
  extern __shared__ uint32_t smu[];
  const uint32_t sb = s2u(smu);
  const int tid  = threadIdx.x;
  const int lane = tid & 31;
  const int wid  = tid >> 5;       // 0..3
  const int quad = lane >> 2;
  const int qt   = lane & 3;
  const int h = blockIdx.y;
  const int sBase = blockIdx.x * BM;

  {
    const uint32_t* qh = g_qhi + ((size_t)sBase*NH + h)*64;
    const uint32_t* ql = g_qlo + ((size_t)sBase*NH + h)*64;
    #pragma unroll
    for (int i = 0; i < 8; i++){
      int f = i*NT + tid;                  // 1024: 64 rows x 16 segs
      int row = f >> 4, seg = f & 15;
      cpa16(sb + (uint32_t)(QH_OFF + row*68 + seg*4)*4u, qh + (size_t)row*NH*64 + seg*4);
      cpa16(sb + (uint32_t)(QL_OFF + row*68 + seg*4)*4u, ql + (size_t)row*NH*64 + seg*4);
    }
  }
  load_chunk(sb, 0, h, 0, tid);
  CP_COMMIT();

  const uint32_t lrow = lane & 7;
  const uint32_t lm   = (uint32_t)lane >> 3;
  const uint32_t qa_h = sb + (uint32_t)(QH_OFF + (wid*16 + (int)lrow + (int)((lm&1)*8))*68 + (int)((lm>>1)*4))*4u;
  const uint32_t qa_l = qa_h + (uint32_t)(64*68)*4u;    // QL_OFF - QH_OFF
  const uint32_t kb_off = (uint32_t)((((lm>>1)*8 + lrow)*68 + (lm&1)*4))*4u;
  const uint32_t vb_off = (uint32_t)((((lm>>1)*8 + lrow)*20 + (lm&1)*4))*4u;

  const int s0 = sBase + wid*16 + quad;
  const int s1 = s0 + 8;
  const int m0r0 = (masks[s0]      != 0), m0r1 = (masks[s1]      != 0);
  const int m1r0 = (masks[TS + s0] != 0), m1r1 = (masks[TS + s1] != 0);
  const int anyr0 = m0r0 | m1r0;
  const int anyr1 = m0r1 | m1r1;
  const unsigned FULL = 0xffffffffu;

  float o[16][4];
  #pragma unroll
  for (int n = 0; n < 16; n++)
    #pragma unroll
    for (int e = 0; e < 4; e++) o[n][e] = 0.f;

  float* o0p = out + (size_t)s0*(size_t)(NH*HD) + (size_t)h*HD + 2*qt;
  float* o1p = out + (size_t)s1*(size_t)(NH*HD) + (size_t)h*HD + 2*qt;

  // ---- base pass (chunks 0..15)
  {
    float l0 = 0.f, l1 = 0.f;
    #pragma unroll 1
    for (int t = 0; t < 16; t++)
      do_chunk(sb, t, h, tid, qa_h, qa_l, kb_off, vb_off, o, 1, 1, l0, l1);

    l0 += __shfl_xor_sync(FULL, l0, 1, 4); l0 += __shfl_xor_sync(FULL, l0, 2, 4);
    l1 += __shfl_xor_sync(FULL, l1, 1, 4); l1 += __shfl_xor_sync(FULL, l1, 2, 4);
    const float w0 = (anyr0 ? 0.5f : 1.0f) / l0;
    const float w1 = (anyr1 ? 0.5f : 1.0f) / l1;
    #pragma unroll
    for (int n = 0; n < 16; n++){
      *(float2*)(o0p + n*8) = make_float2(o[n][0]*w0, o[n][1]*w0);
      *(float2*)(o1p + n*8) = make_float2(o[n][2]*w1, o[n][3]*w1);
      o[n][0] = 0.f; o[n][1] = 0.f; o[n][2] = 0.f; o[n][3] = 0.f;
    }
  }

  // ---- regional pass (chunks 16..47)
  {
    float l0 = 0.f, l1 = 0.f;
    #pragma unroll 1
    for (int t = 16; t < 32; t++)
      do_chunk(sb, t, h, tid, qa_h, qa_l, kb_off, vb_off, o, m0r0, m0r1, l0, l1);
    #pragma unroll 1
    for (int t = 32; t < 48; t++)
      do_chunk(sb, t, h, tid, qa_h, qa_l, kb_off, vb_off, o, m1r0, m1r1, l0, l1);

    l0 += __shfl_xor_sync(FULL, l0, 1, 4); l0 += __shfl_xor_sync(FULL, l0, 2, 4);
    l1 += __shfl_xor_sync(FULL, l1, 1, 4); l1 += __shfl_xor_sync(FULL, l1, 2, 4);
    const float w0 = anyr0 ? (0.5f / l0) : 0.f;
    const float w1 = anyr1 ? (0.5f / l1) : 0.f;
    #pragma unroll
    for (int n = 0; n < 16; n++){
      float2 a = *(const float2*)(o0p + n*8);
      float2 b = *(const float2*)(o1p + n*8);
      a.x += o[n][0]*w0; a.y += o[n][1]*w0;
      b.x += o[n][2]*w1; b.y += o[n][3]*w1;
      *(float2*)(o0p + n*8) = a;
      *(float2*)(o1p + n*8) = b;
    }
  }
}

extern "C" void kernel_launch(void* const* d_in, const int* in_sizes, int n_in,
                              void* d_out, int out_size)
{
  const float* q     = (const float*)d_in[0];
  const float* k     = (const float*)d_in[1];
  const float* v     = (const float*)d_in[2];
  const float* rk    = (const float*)d_in[3];
  const float* rv    = (const float*)d_in[4];
  const int*   masks = (const int*)d_in[5];
  float* out = (float*)d_out;

  prep_k<<<3*16*512*64/256, 256>>>(k, rk);
  prep_q<<<4096*16*64/256, 256>>>(q);
  { dim3 g(8, 16, 3); prep_v<<<g, 256>>>(v, rv); }

  const int smem = SMEM_U32 * 4;   // 90112
  cudaFuncSetAttribute(regional_attn_main,
                       cudaFuncAttributeMaxDynamicSharedMemorySize, smem);
  dim3 grid(TS / BM, NH);   // (64, 16) = 1024 CTAs, 2 per SM
  regional_attn_main<<<grid, NT, smem>>>(masks, out);
}

// round 16
// speedup vs baseline: 1.2019x; 1.2019x over previous
#include <cuda_runtime.h>
#include <cstdint>

#define TS 4096
#define NH 16
#define HD 128
#define NP 512
#define BM 128
#define BN 64
#define NT 256            // 8 warps
#define SCALE 0.08838834764831845f

// ---- device scratch: fp16 planes, packed 2 consecutive elems per u32 ----
__device__ uint32_t g_kfh[3*16*512*64];    // K hi (fp16)
__device__ uint32_t g_kfl[3*16*512*64];    // K lo (fp16 residual)
__device__ uint32_t g_vtf[3*16*128*256];   // V^T fp16, packed key-pairs
__device__ uint32_t g_qf [4096*16*64];     // Q hi only (fp16)

static __device__ __forceinline__ uint32_t s2u(const void* p){
  uint32_t a; asm("{ .reg .u64 t; cvta.to.shared.u64 t, %1; cvt.u32.u64 %0, t; }" : "=r"(a) : "l"(p)); return a;
}
static __device__ __forceinline__ uint16_t f2h(float x){
  uint16_t r; asm("cvt.rn.f16.f32 %0, %1;" : "=h"(r) : "f"(x)); return r;
}
static __device__ __forceinline__ float h2f(uint16_t h){
  float r; asm("cvt.f32.f16 %0, %1;" : "=f"(r) : "h"(h)); return r;
}
static __device__ __forceinline__ uint32_t packh(float x0, float x1){
  uint32_t r; asm("cvt.rn.f16x2.f32 %0, %1, %2;" : "=r"(r) : "f"(x1), "f"(x0)); return r;
}
// fp16 hi/lo split of a float pair
static __device__ __forceinline__ void splitpair_h(float x0, float x1, uint32_t& hi, uint32_t& lo){
  hi = packh(x0, x1);
  float h0 = h2f((uint16_t)(hi & 0xffffu));
  float h1 = h2f((uint16_t)(hi >> 16));
  lo = packh(x0 - h0, x1 - h1);
}
static __device__ __forceinline__ void mma_f16(float* d, const uint32_t* a, const uint32_t* b){
  asm volatile(
    "mma.sync.aligned.m16n8k16.row.col.f32.f16.f16.f32 "
    "{%0,%1,%2,%3}, {%4,%5,%6,%7}, {%8,%9}, {%0,%1,%2,%3};"
    : "+f"(d[0]), "+f"(d[1]), "+f"(d[2]), "+f"(d[3])
    : "r"(a[0]), "r"(a[1]), "r"(a[2]), "r"(a[3]), "r"(b[0]), "r"(b[1]));
}
static __device__ __forceinline__ void ldsm4(uint32_t& r0, uint32_t& r1, uint32_t& r2, uint32_t& r3, uint32_t addr){
  asm volatile("ldmatrix.sync.aligned.m8n8.x4.shared.b16 {%0,%1,%2,%3}, [%4];"
               : "=r"(r0), "=r"(r1), "=r"(r2), "=r"(r3) : "r"(addr));
}
static __device__ __forceinline__ void cpa16(uint32_t dst, const void* src){
  asm volatile("cp.async.cg.shared.global [%0], [%1], 16;" :: "r"(dst), "l"(src) : "memory");
}
#define CP_COMMIT() asm volatile("cp.async.commit_group;" ::: "memory")
#define CP_WAIT0()  asm volatile("cp.async.wait_group 0;" ::: "memory")

// ================= pre-pass kernels =================
__global__ void prep_k(const float* __restrict__ k, const float* __restrict__ rk){
  int g = blockIdx.x * blockDim.x + threadIdx.x;
  int dp = g & 63; int r = g >> 6;
  int j = r & 511; r >>= 9;
  int h = r & 15;  int blk = r >> 4;
  const float* src = (blk == 0)
    ? (k  + ((size_t)j*NH + h)*HD + dp*2)
    : (rk + (((size_t)(blk-1)*NP + j)*NH + h)*HD + dp*2);
  float2 x = *(const float2*)src;
  uint32_t hi, lo; splitpair_h(x.x, x.y, hi, lo);
  g_kfh[g] = hi; g_kfl[g] = lo;
}
__global__ void prep_q(const float* __restrict__ q){
  int g = blockIdx.x * blockDim.x + threadIdx.x;
  float2 x = *(const float2*)(q + (size_t)g*2);
  g_qf[g] = packh(x.x, x.y);
}
__global__ void prep_v(const float* __restrict__ v, const float* __restrict__ rv){
  __shared__ uint16_t sh[128][66];
  int jt  = blockIdx.x;
  int h   = blockIdx.y;
  int blk = blockIdx.z;
  int tid = threadIdx.x;
  const float* src = (blk == 0) ? v : (rv + (size_t)(blk-1)*NP*NH*HD);
  #pragma unroll
  for (int i = 0; i < 8; i++){
    int f = i*256 + tid;
    int j = f >> 5; int d0 = (f & 31) << 2;
    float4 x = *(const float4*)(src + ((size_t)(jt*64 + j)*NH + h)*HD + d0);
    sh[d0+0][j] = f2h(x.x);
    sh[d0+1][j] = f2h(x.y);
    sh[d0+2][j] = f2h(x.z);
    sh[d0+3][j] = f2h(x.w);
  }
  __syncthreads();
  size_t base = ((size_t)(blk*NH + h)*128)*256 + jt*32;
  #pragma unroll
  for (int i = 0; i < 16; i++){
    int u = i*256 + tid;
    int d = u >> 5; int jp = u & 31;
    g_vtf[base + (size_t)d*256 + jp] = ((uint32_t)sh[d][jp*2+1] << 16) | sh[d][jp*2];
  }
}

// ================= main kernel =================
// smem (u32): QF 128x68, KH 2x64x68, KL 2x64x68, VF 2x128x36
#define QF_OFF  0
#define KH_OFF  (QF_OFF + 128*68)          // 8704, + buf*64*68
#define KL_OFF  (KH_OFF + 2*64*68)         // 17408
#define VF_OFF  (KL_OFF + 2*64*68)         // 26112, + buf*128*36
#define SMEM_U32 (VF_OFF + 2*128*36)       // 35328 u32 = 141312 B

static __device__ __forceinline__ void load_chunk(uint32_t sb, int t, int h, int buf, int tid){
  int blk = (t < 8) ? 0 : (1 + ((t - 8) >> 3));
  int j0  = ((t < 8) ? t : ((t - 8) & 7)) * BN;
  const uint32_t* kh = g_kfh + ((size_t)(blk*NH + h)*512 + j0)*64;
  const uint32_t* kl = g_kfl + ((size_t)(blk*NH + h)*512 + j0)*64;
  const uint32_t* vf = g_vtf + ((size_t)(blk*NH + h)*128)*256 + (j0 >> 1);
  uint32_t kdh = sb + (KH_OFF + buf*64*68)*4u;
  uint32_t kdl = sb + (KL_OFF + buf*64*68)*4u;
  uint32_t vdf = sb + (VF_OFF + buf*128*36)*4u;
  #pragma unroll
  for (int i = 0; i < 4; i++){
    int f = i*NT + tid;
    int row = f >> 4, seg = f & 15;        // K: 64 rows x 16 segs
    cpa16(kdh + (uint32_t)(row*68 + seg*4)*4u, kh + (size_t)row*64 + seg*4);
    cpa16(kdl + (uint32_t)(row*68 + seg*4)*4u, kl + (size_t)row*64 + seg*4);
    int vrow = f >> 3, vseg = f & 7;       // V: 128 rows x 8 segs
    cpa16(vdf + (uint32_t)(vrow*36 + vseg*4)*4u, vf + (size_t)vrow*256 + vseg*4);
  }
}

// One 64-key chunk: QK fp16 2-term -> exp -> PV fp16 single-term.
static __device__ __forceinline__ void do_chunk(
    uint32_t sb, int t, int h, int tid,
    uint32_t qa, uint32_t kb_off, uint32_t vb_off,
    float (&o)[16][4], int a0, int a1, float& su0t, float& su1t)
{
  CP_WAIT0();
  __syncthreads();
  if (t + 1 < 24){
    load_chunk(sb, t+1, h, (t+1)&1, tid);
    CP_COMMIT();
  }

  const uint32_t kh_base = sb + (uint32_t)(KH_OFF + (t&1)*64*68)*4u + kb_off;
  const uint32_t kl_base = kh_base + (uint32_t)(2*64*68)*4u;         // KL_OFF - KH_OFF
  const uint32_t vf_base = sb + (uint32_t)(VF_OFF + (t&1)*128*36)*4u + vb_off;

  // ---- QK^T (2-term fp16): S = Qh*Kh + Qh*Kl
  float sf[8][4];
  #pragma unroll
  for (int n = 0; n < 8; n++)
    #pragma unroll
    for (int e = 0; e < 4; e++) sf[n][e] = 0.f;

  #pragma unroll
  for (int ks = 0; ks < 8; ks++){
    uint32_t ah[4];
    ldsm4(ah[0], ah[1], ah[2], ah[3], qa + ks*32u);
    uint32_t B[4][4], C[4][4];
    #pragma unroll
    for (int np = 0; np < 4; np++){
      ldsm4(B[np][0], B[np][1], B[np][2], B[np][3], kh_base + (uint32_t)(np*2*8*68)*4u + ks*32u);
      ldsm4(C[np][0], C[np][1], C[np][2], C[np][3], kl_base + (uint32_t)(np*2*8*68)*4u + ks*32u);
    }
    #pragma unroll
    for (int np = 0; np < 4; np++){
      mma_f16(sf[2*np],   ah, &B[np][0]);
      mma_f16(sf[2*np+1], ah, &B[np][2]);
    }
    #pragma unroll
    for (int np = 0; np < 4; np++){
      mma_f16(sf[2*np],   ah, &C[np][0]);
      mma_f16(sf[2*np+1], ah, &C[np][2]);
    }
  }

  // ---- exp, pack P fp16
  uint32_t pa[8], pb[8];
  float su0 = 0.f, su1 = 0.f;
  #pragma unroll
  for (int n = 0; n < 8; n++){
    float p0 = a0 ? __expf(sf[n][0]*SCALE) : 0.f;
    float p1 = a0 ? __expf(sf[n][1]*SCALE) : 0.f;
    float p2 = a1 ? __expf(sf[n][2]*SCALE) : 0.f;
    float p3 = a1 ? __expf(sf[n][3]*SCALE) : 0.f;
    su0 += p0 + p1; su1 += p2 + p3;
    pa[n] = packh(p0, p1);
    pb[n] = packh(p2, p3);
  }
  su0t += su0; su1t += su1;

  // ---- P@V (single-term fp16): 4 k-steps x 16 n-tiles = 64 MMAs
  #pragma unroll
  for (int s = 0; s < 4; s++){
    uint32_t ph[4] = { pa[2*s], pb[2*s], pa[2*s+1], pb[2*s+1] };
    #pragma unroll
    for (int g = 0; g < 2; g++){
      uint32_t B[4][4];
      #pragma unroll
      for (int i = 0; i < 4; i++){
        int np = g*4 + i;
        ldsm4(B[i][0], B[i][1], B[i][2], B[i][3], vf_base + (uint32_t)(np*2*8*36)*4u + s*32u);
      }
      #pragma unroll
      for (int i = 0; i < 4; i++){
        int np = g*4 + i;
        mma_f16(o[2*np],   ph, &B[i][0]);
        mma_f16(o[2*np+1], ph, &B[i][2]);
      }
    }
  }
}

__global__ __launch_bounds__(NT, 1)
void regional_attn_main(const int* __restrict__ masks, float* __restrict__ out)
{
  extern __shared__ uint32_t smu[];
  const uint32_t sb = s2u(smu);
  const int tid  = threadIdx.x;
  const int lane = tid & 31;
  const int wid  = tid >> 5;
  const int quad = lane >> 2;
  const int qt   = lane & 3;
  const int h = blockIdx.y;
  const int sBase = blockIdx.x * BM;

  {
    const uint32_t* qf = g_qf + ((size_t)sBase*NH + h)*64;
    #pragma unroll
    for (int i = 0; i < 8; i++){
      int f = i*NT + tid;
      int row = f >> 4, seg = f & 15;
      cpa16(sb + (uint32_t)(QF_OFF + row*68 + seg*4)*4u, qf + (size_t)row*NH*64 + seg*4);
    }
  }
  load_chunk(sb, 0, h, 0, tid);
  CP_COMMIT();

  const uint32_t lrow = lane & 7;
  const uint32_t lm   = (uint32_t)lane >> 3;
  const uint32_t qa = sb + (uint32_t)(QF_OFF + (wid*16 + (int)lrow + (int)((lm&1)*8))*68 + (int)((lm>>1)*4))*4u;
  const uint32_t kb_off = (uint32_t)((((lm>>1)*8 + lrow)*68 + (lm&1)*4))*4u;
  const uint32_t vb_off = (uint32_t)((((lm>>1)*8 + lrow)*36 + (lm&1)*4))*4u;

  const int s0 = sBase + wid*16 + quad;
  const int s1 = s0 + 8;
  const int m0r0 = (masks[s0]      != 0), m0r1 = (masks[s1]      != 0);
  const int m1r0 = (masks[TS + s0] != 0), m1r1 = (masks[TS + s1] != 0);
  const int anyr0 = m0r0 | m1r0;
  const int anyr1 = m0r1 | m1r1;
  const unsigned FULL = 0xffffffffu;

  float o[16][4];
  #pragma unroll
  for (int n = 0; n < 16; n++)
    #pragma unroll
    for (int e = 0; e < 4; e++) o[n][e] = 0.f;

  float* o0p = out + (size_t)s0*(size_t)(NH*HD) + (size_t)h*HD + 2*qt;
  float* o1p = out + (size_t)s1*(size_t)(NH*HD) + (size_t)h*HD + 2*qt;

  // ---- base pass (chunks 0..7)
  {
    float l0 = 0.f, l1 = 0.f;
    #pragma unroll 1
    for (int t = 0; t < 8; t++)
      do_chunk(sb, t, h, tid, qa, kb_off, vb_off, o, 1, 1, l0, l1);

    l0 += __shfl_xor_sync(FULL, l0, 1, 4); l0 += __shfl_xor_sync(FULL, l0, 2, 4);
    l1 += __shfl_xor_sync(FULL, l1, 1, 4); l1 += __shfl_xor_sync(FULL, l1, 2, 4);
    const float w0 = (anyr0 ? 0.5f : 1.0f) / l0;
    const float w1 = (anyr1 ? 0.5f : 1.0f) / l1;
    #pragma unroll
    for (int n = 0; n < 16; n++){
      *(float2*)(o0p + n*8) = make_float2(o[n][0]*w0, o[n][1]*w0);
      *(float2*)(o1p + n*8) = make_float2(o[n][2]*w1, o[n][3]*w1);
      o[n][0] = 0.f; o[n][1] = 0.f; o[n][2] = 0.f; o[n][3] = 0.f;
    }
  }

  // ---- regional pass (chunks 8..23)
  {
    float l0 = 0.f, l1 = 0.f;
    #pragma unroll 1
    for (int t = 8; t < 16; t++)
      do_chunk(sb, t, h, tid, qa, kb_off, vb_off, o, m0r0, m0r1, l0, l1);
    #pragma unroll 1
    for (int t = 16; t < 24; t++)
      do_chunk(sb, t, h, tid, qa, kb_off, vb_off, o, m1r0, m1r1, l0, l1);

    l0 += __shfl_xor_sync(FULL, l0, 1, 4); l0 += __shfl_xor_sync(FULL, l0, 2, 4);
    l1 += __shfl_xor_sync(FULL, l1, 1, 4); l1 += __shfl_xor_sync(FULL, l1, 2, 4);
    const float w0 = anyr0 ? (0.5f / l0) : 0.f;
    const float w1 = anyr1 ? (0.5f / l1) : 0.f;
    #pragma unroll
    for (int n = 0; n < 16; n++){
      float2 a = *(const float2*)(o0p + n*8);
      float2 b = *(const float2*)(o1p + n*8);
      a.x += o[n][0]*w0; a.y += o[n][1]*w0;
      b.x += o[n][2]*w1; b.y += o[n][3]*w1;
      *(float2*)(o0p + n*8) = a;
      *(float2*)(o1p + n*8) = b;
    }
  }
}

extern "C" void kernel_launch(void* const* d_in, const int* in_sizes, int n_in,
                              void* d_out, int out_size)
{
  const float* q     = (const float*)d_in[0];
  const float* k     = (const float*)d_in[1];
  const float* v     = (const float*)d_in[2];
  const float* rk    = (const float*)d_in[3];
  const float* rv    = (const float*)d_in[4];
  const int*   masks = (const int*)d_in[5];
  float* out = (float*)d_out;

  prep_k<<<3*16*512*64/256, 256>>>(k, rk);
  prep_q<<<4096*16*64/256, 256>>>(q);
  { dim3 g(8, 16, 3); prep_v<<<g, 256>>>(v, rv); }

  const int smem = SMEM_U32 * 4;   // 141312
  cudaFuncSetAttribute(regional_attn_main,
                       cudaFuncAttributeMaxDynamicSharedMemorySize, smem);
  dim3 grid(TS / BM, NH);   // (32, 16)
  regional_attn_main<<<grid, NT, smem>>>(masks, out);
}